// round 7
// baseline (speedup 1.0000x reference)
#include <cuda_runtime.h>
#include <math.h>
#include <stdint.h>
#include <mma.h>

using namespace nvcuda;

#define LL 512
#define BB 64
#define EE 256
#define HH 256
#define HID 512
#define NG 1024      // 4*H gate rows
#define MM 32768     // LL*BB
#define CC 5
#define TAG_START 3
#define TAG_STOP 4
#define IMPOSSIBLE_F (-1e4f)

typedef unsigned long long ull;

// ---------------- packed fp32x2 FMA helpers (SASS FFMA2, PTX-only) ------------
__device__ __forceinline__ void fma2(ull& acc, ull a, ull b) {
    asm("fma.rn.f32x2 %0, %1, %2, %0;" : "+l"(acc) : "l"(a), "l"(b));
}
__device__ __forceinline__ ull pk2(float x, float y) {
    ull r; asm("mov.b64 %0, {%1, %2};" : "=l"(r) : "f"(x), "f"(y)); return r;
}
__device__ __forceinline__ float red2(ull v) {
    float x, y; asm("mov.b64 {%0, %1}, %2;" : "=f"(x), "=f"(y) : "l"(v)); return x + y;
}
__device__ __forceinline__ float tf32r(float x) {
    uint32_t u; asm("cvt.rna.tf32.f32 %0, %1;" : "=r"(u) : "f"(x));
    return __uint_as_float(u);
}

// ---------------- scratch (device globals; no cudaMalloc allowed) -------------
__device__ float g_embx [(size_t)LL * BB * EE];
__device__ float g_bufA [(size_t)LL * BB * HID];
__device__ float g_bufB [(size_t)LL * BB * HID];
__device__ float g_gates[(size_t)2 * NG * MM];        // G^T: [dir][n][m]
__device__ float g_emit [(size_t)LL * BB * CC];
__device__ int   g_bp   [(size_t)LL * BB * CC];
__device__ unsigned g_flags[128];                     // per-CTA step flags [dir][64]

__global__ void init_bar_k() { if (threadIdx.x < 128) g_flags[threadIdx.x] = 0u; }

// ---------------- embedding gather --------------------------------------------
__global__ void embed_k(const int* __restrict__ xs, const float* __restrict__ emb,
                        float* __restrict__ X)
{
    size_t i = (size_t)blockIdx.x * blockDim.x + threadIdx.x;
    size_t total = (size_t)LL * BB * (EE / 4);
    if (i >= total) return;
    int e4 = (int)(i % (EE / 4));
    size_t p = i / (EE / 4);
    int b = (int)(p % BB);
    int t = (int)(p / BB);
    int tok = xs[(size_t)b * LL + t];
    *(float4*)&X[p * EE + e4 * 4] = *(const float4*)&emb[(size_t)tok * EE + e4 * 4];
}

// ---------------- wmma tf32 input-projection GEMM, transposed output ----------
// GT[dir][n][m] = A[m,:]·W[dir][n,:] + bias[n]
// CTA tile M=128 x N=128, K-chunks of 32, 8 warps (2m x 4n), warp tile 64x32.
#define GP 36
#define GBUF (128 * GP)
#define BT_STRIDE 132
#define GSM_TOT ((4 * GBUF + 16 * BT_STRIDE) * 4)     // 82176 bytes

__global__ __launch_bounds__(256) void gemm_wmma_k(
    const float* __restrict__ A,
    const float* __restrict__ W0, const float* __restrict__ W1,
    const float* __restrict__ bias0, const float* __restrict__ bias1,
    float* __restrict__ G, int K)
{
    extern __shared__ float sm[];
    float* Abuf[2] = { sm,             sm + GBUF     };
    float* Wbuf[2] = { sm + 2 * GBUF,  sm + 3 * GBUF };
    float* btile   = sm + 4 * GBUF;                   // [16][132], rows identical

    int tid = threadIdx.x, wid = tid >> 5;
    int m0 = blockIdx.x * 128;
    int n0 = blockIdx.y * 128;
    int dir = blockIdx.z;
    const float* W    = dir ? W1 : W0;
    const float* bias = dir ? bias1 : bias0;
    float* Gt = G + (size_t)dir * NG * MM;

    int wm = wid >> 2;            // 0..1  (64 rows each)
    int wn = wid & 3;             // 0..3  (32 cols each)

    // bias tile (each of 16 rows holds bias[n0..n0+127])
#pragma unroll
    for (int u = 0; u < 8; u++) {
        int idx = tid + u * 256;
        int r = idx >> 7, c = idx & 127;
        btile[r * BT_STRIDE + c] = bias[n0 + c];
    }

    auto stage = [&](int c, int buf) {
        const float* Asrc = A + (size_t)m0 * K + c * 32;
        const float* Wsrc = W + (size_t)n0 * K + c * 32;
        float* ad = Abuf[buf];
        float* wd = Wbuf[buf];
#pragma unroll
        for (int u = 0; u < 4; u++) {
            int idx = tid + u * 256;
            int row = idx >> 3, c4 = idx & 7;
            float4 v = *(const float4*)&Asrc[(size_t)row * K + c4 * 4];
            v.x = tf32r(v.x); v.y = tf32r(v.y); v.z = tf32r(v.z); v.w = tf32r(v.w);
            *(float4*)&ad[row * GP + c4 * 4] = v;
            float4 q = *(const float4*)&Wsrc[(size_t)row * K + c4 * 4];
            q.x = tf32r(q.x); q.y = tf32r(q.y); q.z = tf32r(q.z); q.w = tf32r(q.w);
            *(float4*)&wd[row * GP + c4 * 4] = q;
        }
    };

    stage(0, 0);
    __syncthreads();

    // accumulators pre-loaded with bias (all rows of btile identical)
    wmma::fragment<wmma::accumulator, 16, 16, 8, float> acc[4][2];
#pragma unroll
    for (int i = 0; i < 4; i++)
#pragma unroll
        for (int j = 0; j < 2; j++)
            wmma::load_matrix_sync(acc[i][j], btile + wn * 32 + j * 16,
                                   BT_STRIDE, wmma::mem_row_major);

    const int NC = K >> 5;
    for (int c = 0; c < NC; c++) {
        int cur = c & 1;
        if (c + 1 < NC) stage(c + 1, cur ^ 1);

        const float* ab = Abuf[cur] + wm * 64 * GP;
        const float* wb = Wbuf[cur] + wn * 32 * GP;
#pragma unroll
        for (int kk = 0; kk < 4; kk++) {
            wmma::fragment<wmma::matrix_a, 16, 16, 8, wmma::precision::tf32,
                           wmma::row_major> af[4];
            wmma::fragment<wmma::matrix_b, 16, 16, 8, wmma::precision::tf32,
                           wmma::col_major> bf[2];
#pragma unroll
            for (int i = 0; i < 4; i++)
                wmma::load_matrix_sync(af[i], ab + i * 16 * GP + kk * 8, GP);
#pragma unroll
            for (int j = 0; j < 2; j++)
                wmma::load_matrix_sync(bf[j], wb + j * 16 * GP + kk * 8, GP);
#pragma unroll
            for (int i = 0; i < 4; i++)
#pragma unroll
                for (int j = 0; j < 2; j++)
                    wmma::mma_sync(acc[i][j], af[i], bf[j], acc[i][j]);
        }
        __syncthreads();
    }

    // store transposed: GT[n][m] = col-major view of (m,n) tile with ldm = MM
#pragma unroll
    for (int i = 0; i < 4; i++)
#pragma unroll
        for (int j = 0; j < 2; j++) {
            float* gt = Gt + (size_t)(n0 + wn * 32 + j * 16) * MM
                           + (m0 + wm * 64 + i * 16);
            wmma::store_matrix_sync(gt, acc[i][j], MM, wmma::mem_col_major);
        }
}

// ---------------- persistent per-layer LSTM recurrence ------------------------
// 128 CTAs: dir = bx>>6, unit group j0 = (bx&63)*4. 256 threads:
//   jj = tid>>6 (unit), bg = (tid>>3)&7 (8 batches), ks = tid&7 (32-k segment).
// Whh in registers (w2[4 gates][16] packed pairs). h in smem, conflict-free:
//   hs row stride 288 (=0 mod 32 banks), kseg offset 36 (bank +4 per kseg).
#define HS_S 288
#define SM_GS   (64 * HS_S)              // 18432 floats
#define SM_HOUT (SM_GS + 16 * 64)        // +1024
#define LSTM_SMEM ((SM_HOUT + 64 * 8) * 4)   // 79872 bytes

__global__ __launch_bounds__(256, 1) void lstm_layer_k(
    const float* __restrict__ Gt,
    const float* __restrict__ Whh0, const float* __restrict__ Whh1,
    float* __restrict__ y, int lbase)
{
    extern __shared__ float sm[];
    float* hs   = sm;
    float* Gs   = sm + SM_GS;            // [16 rows][64 b]
    float* hout = sm + SM_HOUT;          // [64 b][8]

    int bx  = blockIdx.x;
    int dir = bx >> 6;
    int j0  = (bx & 63) * 4;
    int tid = threadIdx.x;
    int jj = tid >> 6;
    int bg = (tid >> 3) & 7;
    int ks = tid & 7;
    int b0 = bg * 8;
    int j  = j0 + jj;
    const float* Whh = dir ? Whh1 : Whh0;
    const float* Gd  = Gt + (size_t)dir * NG * MM;

    // ---- load this thread's Whh slice into registers (step-invariant) ----
    ull w2[4][16];
#pragma unroll
    for (int g = 0; g < 4; g++) {
        const float* wr = &Whh[(size_t)(g * 256 + j) * HH + ks * 32];
#pragma unroll
        for (int q = 0; q < 8; q++) {
            ulonglong2 v = *(const ulonglong2*)&wr[q * 4];
            w2[g][2 * q] = v.x; w2[g][2 * q + 1] = v.y;
        }
    }

    float cst[8];
#pragma unroll
    for (int i = 0; i < 8; i++) cst[i] = 0.f;

    // G gather indices (coalesced: warp reads 32 consecutive b at fixed row)
    size_t gaddr[4];
    int grow[4], gbv[4];
#pragma unroll
    for (int u = 0; u < 4; u++) {
        int v = tid + u * 256;
        int r = v >> 6, b = v & 63;
        grow[u] = r; gbv[u] = b;
        gaddr[u] = (size_t)((r >> 2) * 256 + j0 + (r & 3)) * MM + b;
    }

    unsigned* myflag = &g_flags[dir * 64 + (bx & 63)];

    for (int s = 0; s < LL; s++) {
        int t     = dir ? (LL - 1 - s) : s;
        int tprev = dir ? (t + 1) : (t - 1);

        // prefetch input-projection gates for this step (coalesced from GT)
        float glo[4];
#pragma unroll
        for (int u = 0; u < 4; u++)
            glo[u] = Gd[gaddr[u] + (size_t)t * 64];

        if (s > 0) {
            // stage h_prev into swizzled hs: 64 b x 256 floats = 4096 float4
            const float* yb = y + ((size_t)tprev * BB) * HID + dir * HH;
#pragma unroll
            for (int u = 0; u < 16; u++) {
                int v = tid + u * 256;
                int b = v >> 6, k4 = v & 63;
                float4 hv = *(const float4*)&yb[(size_t)b * HID + k4 * 4];
                *(float4*)&hs[b * HS_S + (k4 >> 3) * 36 + (k4 & 7) * 4] = hv;
            }
        }
        __syncthreads();                                      // hs ready

#pragma unroll
        for (int u = 0; u < 4; u++)
            Gs[grow[u] * 64 + gbv[u]] = glo[u];

        float accf[4][8];
        if (s > 0) {
            ull acc2[4][8];
#pragma unroll
            for (int g = 0; g < 4; g++)
#pragma unroll
                for (int i = 0; i < 8; i++) acc2[g][i] = pk2(0.f, 0.f);

            int hoff = ks * 36;
#pragma unroll
            for (int kc = 0; kc < 8; kc++) {
                ulonglong2 u4[4];
#pragma unroll
                for (int i = 0; i < 4; i++)
                    u4[i] = *(const ulonglong2*)&hs[(b0 + i) * HS_S + hoff + kc * 4];
#pragma unroll
                for (int g = 0; g < 4; g++)
#pragma unroll
                    for (int i = 0; i < 4; i++) {
                        fma2(acc2[g][i], w2[g][2 * kc],     u4[i].x);
                        fma2(acc2[g][i], w2[g][2 * kc + 1], u4[i].y);
                    }
#pragma unroll
                for (int i = 0; i < 4; i++)
                    u4[i] = *(const ulonglong2*)&hs[(b0 + 4 + i) * HS_S + hoff + kc * 4];
#pragma unroll
                for (int g = 0; g < 4; g++)
#pragma unroll
                    for (int i = 0; i < 4; i++) {
                        fma2(acc2[g][4 + i], w2[g][2 * kc],     u4[i].x);
                        fma2(acc2[g][4 + i], w2[g][2 * kc + 1], u4[i].y);
                    }
            }
#pragma unroll
            for (int g = 0; g < 4; g++)
#pragma unroll
                for (int i = 0; i < 8; i++) accf[g][i] = red2(acc2[g][i]);
            // reduce across 8 k-segments (ks in lane bits 0..2)
#pragma unroll
            for (int off = 4; off > 0; off >>= 1)
#pragma unroll
                for (int g = 0; g < 4; g++)
#pragma unroll
                    for (int i = 0; i < 8; i++)
                        accf[g][i] += __shfl_down_sync(0xffffffffu, accf[g][i], off);
        } else {
#pragma unroll
            for (int g = 0; g < 4; g++)
#pragma unroll
                for (int i = 0; i < 8; i++) accf[g][i] = 0.f;
        }
        __syncthreads();                                      // Gs ready

        if (ks == 0) {
#pragma unroll
            for (int i = 0; i < 8; i++) {
                int b = b0 + i;
                float ai = accf[0][i] + Gs[(0  + jj) * 64 + b];
                float af = accf[1][i] + Gs[(4  + jj) * 64 + b];
                float ag = accf[2][i] + Gs[(8  + jj) * 64 + b];
                float ao = accf[3][i] + Gs[(12 + jj) * 64 + b];
                float ig = 1.f / (1.f + expf(-ai));
                float fg = 1.f / (1.f + expf(-af));
                float gg = tanhf(ag);
                float og = 1.f / (1.f + expf(-ao));
                cst[i] = fg * cst[i] + ig * gg;
                hout[b * 8 + jj] = og * tanhf(cst[i]);
            }
        }
        __syncthreads();                                      // hout ready

        if (tid < 64) {
            float4 hv = *(const float4*)&hout[tid * 8];
            *(float4*)&y[((size_t)t * BB + tid) * HID + dir * HH + j0] = hv;
        }
        __syncthreads();                                      // y writes done

        if (s + 1 < LL) {
            unsigned tgt = (unsigned)(lbase + s + 1);
            if (tid == 0)
                asm volatile("st.release.gpu.global.u32 [%0], %1;"
                             :: "l"(myflag), "r"(tgt) : "memory");
            if (tid < 64) {
                unsigned* fl = &g_flags[dir * 64 + tid];
                unsigned v;
                do {
                    asm volatile("ld.acquire.gpu.global.u32 %0, [%1];"
                                 : "=r"(v) : "l"(fl));
                } while (v < tgt);
            }
            __syncthreads();
        }
    }
}

// ---------------- FC -----------------------------------------------------------
__global__ void fc_k(const float* __restrict__ feat, const float* __restrict__ Wfc,
                     const float* __restrict__ bfc, float* __restrict__ emit)
{
    int gw = (int)(((size_t)blockIdx.x * blockDim.x + threadIdx.x) >> 5);
    int lane = threadIdx.x & 31;
    if (gw >= LL * BB) return;
    const float* f = feat + (size_t)gw * HID;
    float acc[CC] = {0.f, 0.f, 0.f, 0.f, 0.f};
#pragma unroll
    for (int i = 0; i < HID / 32; i++) {
        int k = lane + i * 32;
        float fv = f[k];
#pragma unroll
        for (int cc = 0; cc < CC; cc++) acc[cc] += fv * Wfc[cc * HID + k];
    }
#pragma unroll
    for (int off = 16; off > 0; off >>= 1)
#pragma unroll
        for (int cc = 0; cc < CC; cc++)
            acc[cc] += __shfl_down_sync(0xffffffffu, acc[cc], off);
    if (lane == 0)
#pragma unroll
        for (int cc = 0; cc < CC; cc++)
            emit[(size_t)gw * CC + cc] = acc[cc] + bfc[cc];
}

// ---------------- Viterbi + backtrace ------------------------------------------
__global__ void viterbi_k(const float* __restrict__ emit, const float* __restrict__ trans,
                          int* __restrict__ bp, float* __restrict__ out, long long osz)
{
    int b = blockIdx.x;
    int lane = threadIdx.x;
    float tr[CC];
    if (lane < CC)
#pragma unroll
        for (int f = 0; f < CC; f++) tr[f] = trans[lane * CC + f];
    float score = (lane == TAG_START) ? 0.f : IMPOSSIBLE_F;

    for (int t = 0; t < LL; t++) {
        float sc[CC];
#pragma unroll
        for (int f = 0; f < CC; f++) sc[f] = __shfl_sync(0xffffffffu, score, f);
        if (lane < CC) {
            float best = sc[0] + tr[0];
            int arg = 0;
#pragma unroll
            for (int f = 1; f < CC; f++) {
                float v = sc[f] + tr[f];
                if (v > best) { best = v; arg = f; }
            }
            bp[((size_t)t * BB + b) * CC + lane] = arg;
            score = best + emit[((size_t)t * BB + b) * CC + lane];
        }
    }
    if (lane < CC) score += trans[TAG_STOP * CC + lane];
    float sc[CC];
#pragma unroll
    for (int f = 0; f < CC; f++) sc[f] = __shfl_sync(0xffffffffu, score, f);
    if (lane == 0) {
        float best = sc[0];
        int tag = 0;
#pragma unroll
        for (int f = 1; f < CC; f++)
            if (sc[f] > best) { best = sc[f]; tag = f; }
        if (b < osz) out[b] = best;
        long long tb = 64;
        long long o = tb + (long long)b * LL + (LL - 1);
        if (o < osz) out[o] = (float)tag;
        for (int t = LL - 1; t >= 1; t--) {
            tag = bp[((size_t)t * BB + b) * CC + tag];
            o = tb + (long long)b * LL + (t - 1);
            if (o < osz) out[o] = (float)tag;
        }
    }
}

// ---------------- features [t][b][k] -> out [b][t][k] --------------------------
__global__ void feat_out_k(const float* __restrict__ feat, float* __restrict__ out,
                           long long osz)
{
    size_t i = (size_t)blockIdx.x * blockDim.x + threadIdx.x;
    size_t total = (size_t)LL * BB * HID / 4;
    if (i >= total) return;
    int k4 = (int)(i % (HID / 4));
    size_t p = i / (HID / 4);
    int b = (int)(p % BB);
    int t = (int)(p / BB);
    long long o = 32832LL + ((long long)b * LL + t) * HID + k4 * 4;
    if (o + 3 < osz)
        *(float4*)&out[o] = *(const float4*)&feat[p * HID + k4 * 4];
}

__global__ void mask_out_k(float* __restrict__ out, long long osz)
{
    long long i = (long long)blockIdx.x * blockDim.x + threadIdx.x;
    if (i >= (long long)BB * LL) return;
    long long o = 16810048LL + i;
    if (o < osz) out[o] = 1.0f;
}

// ---------------- launch --------------------------------------------------------
extern "C" void kernel_launch(void* const* d_in, const int* in_sizes, int n_in,
                              void* d_out, int out_size)
{
    const int*   xs    = (const int*)  d_in[0];
    const float* emb   = (const float*)d_in[1];
    const float* Wih0  = (const float*)d_in[2];
    const float* Whh0  = (const float*)d_in[3];
    const float* b0    = (const float*)d_in[4];
    const float* WihL  = (const float*)d_in[5];
    const float* WhhL  = (const float*)d_in[6];
    const float* bL    = (const float*)d_in[7];
    const float* Wfc   = (const float*)d_in[8];
    const float* bfc   = (const float*)d_in[9];
    const float* trans = (const float*)d_in[10];
    float* out = (float*)d_out;
    long long osz = out_size;

    float *pX, *pA, *pB, *pG, *pE;
    int* pBP;
    cudaGetSymbolAddress((void**)&pX,  g_embx);
    cudaGetSymbolAddress((void**)&pA,  g_bufA);
    cudaGetSymbolAddress((void**)&pB,  g_bufB);
    cudaGetSymbolAddress((void**)&pG,  g_gates);
    cudaGetSymbolAddress((void**)&pE,  g_emit);
    cudaGetSymbolAddress((void**)&pBP, g_bp);

    cudaFuncSetAttribute(lstm_layer_k, cudaFuncAttributeMaxDynamicSharedMemorySize,
                         LSTM_SMEM);
    cudaFuncSetAttribute(gemm_wmma_k, cudaFuncAttributeMaxDynamicSharedMemorySize,
                         GSM_TOT);

    init_bar_k<<<1, 128>>>();

    {
        size_t total = (size_t)LL * BB * (EE / 4);
        embed_k<<<(unsigned)((total + 255) / 256), 256>>>(xs, emb, pX);
    }

    const float* x = pX;
    int K = EE;
    for (int l = 0; l < 4; l++) {
        const float *WihF, *WihB, *WhhF, *WhhB, *bF, *bBk;
        if (l == 0) {
            WihF = Wih0;                 WihB = Wih0 + (size_t)NG * EE;
            WhhF = Whh0;                 WhhB = Whh0 + (size_t)NG * HH;
            bF   = b0;                   bBk  = b0 + NG;
        } else {
            size_t base = (size_t)(l - 1) * 2;
            WihF = WihL + base * NG * HID;       WihB = WihL + (base + 1) * NG * HID;
            WhhF = WhhL + base * NG * HH;        WhhB = WhhL + (base + 1) * NG * HH;
            bF   = bL + base * NG;               bBk  = bL + (base + 1) * NG;
        }
        float* y = (l & 1) ? pB : pA;

        dim3 ggrid(MM / 128, NG / 128, 2);
        gemm_wmma_k<<<ggrid, 256, GSM_TOT>>>(x, WihF, WihB, bF, bBk, pG, K);

        lstm_layer_k<<<128, 256, LSTM_SMEM>>>(pG, WhhF, WhhB, y, l * LL);

        x = y;
        K = HID;
    }

    fc_k<<<(LL * BB * 32) / 256, 256>>>(x, Wfc, bfc, pE);
    viterbi_k<<<BB, 32>>>(pE, trans, pBP, out, osz);
    {
        size_t total = (size_t)LL * BB * HID / 4;
        feat_out_k<<<(unsigned)((total + 255) / 256), 256>>>(x, out, osz);
    }
    mask_out_k<<<(BB * LL + 255) / 256, 256>>>(out, osz);
}

// round 9
// speedup vs baseline: 1.2740x; 1.2740x over previous
#include <cuda_runtime.h>
#include <math.h>
#include <stdint.h>
#include <mma.h>

using namespace nvcuda;

#define LL 512
#define BB 64
#define EE 256
#define HH 256
#define HID 512
#define NG 1024      // 4*H gate rows
#define MM 32768     // LL*BB
#define CC 5
#define TAG_START 3
#define TAG_STOP 4
#define IMPOSSIBLE_F (-1e4f)

typedef unsigned long long ull;

// ---------------- packed fp32x2 FMA helpers (SASS FFMA2, PTX-only) ------------
__device__ __forceinline__ void fma2(ull& acc, ull a, ull b) {
    asm("fma.rn.f32x2 %0, %1, %2, %0;" : "+l"(acc) : "l"(a), "l"(b));
}
__device__ __forceinline__ ull pk2(float x, float y) {
    ull r; asm("mov.b64 %0, {%1, %2};" : "=l"(r) : "f"(x), "f"(y)); return r;
}
__device__ __forceinline__ float red2(ull v) {
    float x, y; asm("mov.b64 {%0, %1}, %2;" : "=f"(x), "=f"(y) : "l"(v)); return x + y;
}
__device__ __forceinline__ float tf32r(float x) {
    uint32_t u; asm("cvt.rna.tf32.f32 %0, %1;" : "=r"(u) : "f"(x));
    return __uint_as_float(u);
}

// ---------------- scratch (device globals; no cudaMalloc allowed) -------------
__device__ float g_embx [(size_t)LL * BB * EE];
__device__ float g_bufA [(size_t)LL * BB * HID];
__device__ float g_bufB [(size_t)LL * BB * HID];
__device__ float g_gates[(size_t)2 * NG * MM];        // G^T: [dir][n][m]
__device__ float g_emit [(size_t)LL * BB * CC];
__device__ int   g_bp   [(size_t)LL * BB * CC];
__device__ unsigned g_flags[128];                     // per-CTA step flags [dir][64]

__global__ void init_bar_k() { if (threadIdx.x < 128) g_flags[threadIdx.x] = 0u; }

// ---------------- embedding gather --------------------------------------------
__global__ void embed_k(const int* __restrict__ xs, const float* __restrict__ emb,
                        float* __restrict__ X)
{
    size_t i = (size_t)blockIdx.x * blockDim.x + threadIdx.x;
    size_t total = (size_t)LL * BB * (EE / 4);
    if (i >= total) return;
    int e4 = (int)(i % (EE / 4));
    size_t p = i / (EE / 4);
    int b = (int)(p % BB);
    int t = (int)(p / BB);
    int tok = xs[(size_t)b * LL + t];
    *(float4*)&X[p * EE + e4 * 4] = *(const float4*)&emb[(size_t)tok * EE + e4 * 4];
}

// ---------------- wmma tf32 input-projection GEMM, transposed output ----------
// GT[dir][n][m] = A[m,:]·W[dir][n,:] + bias[n]
#define GP 36
#define GBUF (128 * GP)
#define BT_STRIDE 132
#define GSM_TOT ((4 * GBUF + 16 * BT_STRIDE) * 4)     // 82176 bytes

__global__ __launch_bounds__(256) void gemm_wmma_k(
    const float* __restrict__ A,
    const float* __restrict__ W0, const float* __restrict__ W1,
    const float* __restrict__ bias0, const float* __restrict__ bias1,
    float* __restrict__ G, int K)
{
    extern __shared__ float sm[];
    float* Abuf[2] = { sm,             sm + GBUF     };
    float* Wbuf[2] = { sm + 2 * GBUF,  sm + 3 * GBUF };
    float* btile   = sm + 4 * GBUF;                   // [16][132], rows identical

    int tid = threadIdx.x, wid = tid >> 5;
    int m0 = blockIdx.x * 128;
    int n0 = blockIdx.y * 128;
    int dir = blockIdx.z;
    const float* W    = dir ? W1 : W0;
    const float* bias = dir ? bias1 : bias0;
    float* Gt = G + (size_t)dir * NG * MM;

    int wm = wid >> 2;
    int wn = wid & 3;

#pragma unroll
    for (int u = 0; u < 8; u++) {
        int idx = tid + u * 256;
        int r = idx >> 7, c = idx & 127;
        btile[r * BT_STRIDE + c] = bias[n0 + c];
    }

    auto stage = [&](int c, int buf) {
        const float* Asrc = A + (size_t)m0 * K + c * 32;
        const float* Wsrc = W + (size_t)n0 * K + c * 32;
        float* ad = Abuf[buf];
        float* wd = Wbuf[buf];
#pragma unroll
        for (int u = 0; u < 4; u++) {
            int idx = tid + u * 256;
            int row = idx >> 3, c4 = idx & 7;
            float4 v = *(const float4*)&Asrc[(size_t)row * K + c4 * 4];
            v.x = tf32r(v.x); v.y = tf32r(v.y); v.z = tf32r(v.z); v.w = tf32r(v.w);
            *(float4*)&ad[row * GP + c4 * 4] = v;
            float4 q = *(const float4*)&Wsrc[(size_t)row * K + c4 * 4];
            q.x = tf32r(q.x); q.y = tf32r(q.y); q.z = tf32r(q.z); q.w = tf32r(q.w);
            *(float4*)&wd[row * GP + c4 * 4] = q;
        }
    };

    stage(0, 0);
    __syncthreads();

    wmma::fragment<wmma::accumulator, 16, 16, 8, float> acc[4][2];
#pragma unroll
    for (int i = 0; i < 4; i++)
#pragma unroll
        for (int j = 0; j < 2; j++)
            wmma::load_matrix_sync(acc[i][j], btile + wn * 32 + j * 16,
                                   BT_STRIDE, wmma::mem_row_major);

    const int NC = K >> 5;
    for (int c = 0; c < NC; c++) {
        int cur = c & 1;
        if (c + 1 < NC) stage(c + 1, cur ^ 1);

        const float* ab = Abuf[cur] + wm * 64 * GP;
        const float* wb = Wbuf[cur] + wn * 32 * GP;
#pragma unroll
        for (int kk = 0; kk < 4; kk++) {
            wmma::fragment<wmma::matrix_a, 16, 16, 8, wmma::precision::tf32,
                           wmma::row_major> af[4];
            wmma::fragment<wmma::matrix_b, 16, 16, 8, wmma::precision::tf32,
                           wmma::col_major> bf[2];
#pragma unroll
            for (int i = 0; i < 4; i++)
                wmma::load_matrix_sync(af[i], ab + i * 16 * GP + kk * 8, GP);
#pragma unroll
            for (int j = 0; j < 2; j++)
                wmma::load_matrix_sync(bf[j], wb + j * 16 * GP + kk * 8, GP);
#pragma unroll
            for (int i = 0; i < 4; i++)
#pragma unroll
                for (int j = 0; j < 2; j++)
                    wmma::mma_sync(acc[i][j], af[i], bf[j], acc[i][j]);
        }
        __syncthreads();
    }

#pragma unroll
    for (int i = 0; i < 4; i++)
#pragma unroll
        for (int j = 0; j < 2; j++) {
            float* gt = Gt + (size_t)(n0 + wn * 32 + j * 16) * MM
                           + (m0 + wm * 64 + i * 16);
            wmma::store_matrix_sync(gt, acc[i][j], MM, wmma::mem_col_major);
        }
}

// ---------------- persistent per-layer LSTM recurrence ------------------------
// 128 CTAs: dir = bx>>6, unit group j0 = (bx&63)*4. 256 threads:
//   warp w: bh = w&1, kc = w>>1 (k-quarter).  lane -> b = lane + 32*bh.
// Per step: thread holds h[b][kc*64..+63] in regs (32 ull), streams 16 weight
// rows from smem via warp-broadcast LDS, accumulates acc[16] (FFMA2).
// Partials reduced across kc warps through smem; activation = 1 thread/(b,unit).
#define HS_S 260                         // h row stride (65*4: phase-distinct)
#define SMW  0                           // ws[16][256]            4096 floats
#define SMH  4096                        // hs[64][HS_S]           16640
#define SMG  (SMH + 64 * HS_S)           // Gs[16][64]             1024
#define SMP  (SMG + 1024)                // part[4][16][64]        4096
#define SMO  (SMP + 4096)                // hout[4][64]            256
#define LSTM_SMEM ((SMO + 256) * 4)      // 104448 bytes

__global__ __launch_bounds__(256, 1) void lstm_layer_k(
    const float* __restrict__ Gt,
    const float* __restrict__ Whh0, const float* __restrict__ Whh1,
    float* __restrict__ y, int lbase)
{
    extern __shared__ float sm[];
    float* ws   = sm + SMW;
    float* hs   = sm + SMH;
    float* Gs   = sm + SMG;
    float* part = sm + SMP;
    float* hout = sm + SMO;

    int bx  = blockIdx.x;
    int dir = bx >> 6;
    int j0  = (bx & 63) * 4;
    int tid = threadIdx.x;
    int lane = tid & 31, wid = tid >> 5;
    int bh = wid & 1, kc = wid >> 1;
    int b  = lane + 32 * bh;             // this thread's batch (dot phase)
    int kb = kc * 64;                    // k base
    const float* Whh = dir ? Whh1 : Whh0;
    const float* Gd  = Gt + (size_t)dir * NG * MM;

    // ---- stage Whh rows into smem once: ws[r][k], r = gate*4 + unit ----------
#pragma unroll
    for (int u = 0; u < 4; u++) {
        int idx = tid + u * 256;         // 1024 float4
        int r = idx >> 6, k4 = idx & 63;
        int g = r >> 2, un = r & 3;
        *(float4*)&ws[r * 256 + k4 * 4] =
            *(const float4*)&Whh[(size_t)(g * 256 + j0 + un) * HH + k4 * 4];
    }

    // activation-phase identity: one thread per (batch, unit)
    int ab = tid & 63, au = tid >> 6;
    float cst = 0.f;

    // G gather indices (coalesced from GT)
    size_t gaddr[4];
    int grow[4], gbv[4];
#pragma unroll
    for (int u = 0; u < 4; u++) {
        int v = tid + u * 256;
        int r = v >> 6, bb = v & 63;
        grow[u] = r; gbv[u] = bb;
        gaddr[u] = (size_t)((r >> 2) * 256 + j0 + (r & 3)) * MM + bb;
    }

    unsigned* myflag = &g_flags[dir * 64 + (bx & 63)];
    __syncthreads();                     // ws ready

    for (int s = 0; s < LL; s++) {
        int t     = dir ? (LL - 1 - s) : s;
        int tprev = dir ? (t + 1) : (t - 1);

        // prefetch input-projection gates (gmem, coalesced)
        float glo[4];
#pragma unroll
        for (int u = 0; u < 4; u++)
            glo[u] = Gd[gaddr[u] + (size_t)t * 64];

        if (s > 0) {
            // stage h_prev: 64 b x 256 k = 4096 float4, 16 per thread
            const float* yb = y + ((size_t)tprev * BB) * HID + dir * HH;
#pragma unroll
            for (int u = 0; u < 16; u++) {
                int v = tid + u * 256;
                int b2 = v >> 6, k4 = v & 63;
                float4 hv = *(const float4*)&yb[(size_t)b2 * HID + k4 * 4];
                *(float4*)&hs[b2 * HS_S + k4 * 4] = hv;
            }
        }
        __syncthreads();                 // hs ready

#pragma unroll
        for (int u = 0; u < 4; u++)
            Gs[grow[u] * 64 + gbv[u]] = glo[u];

        if (s > 0) {
            // fill h regs: 64 floats = 16 LDS.128, conflict-free (stride 65*4B)
            ull h2[32];
#pragma unroll
            for (int q = 0; q < 16; q++) {
                ulonglong2 hv = *(const ulonglong2*)&hs[b * HS_S + kb + q * 4];
                h2[2 * q] = hv.x; h2[2 * q + 1] = hv.y;
            }
            // dot: stream 16 weight rows (broadcast LDS), 16 indep acc chains
            ull acc[16];
#pragma unroll
            for (int r = 0; r < 16; r++) acc[r] = pk2(0.f, 0.f);
#pragma unroll
            for (int q = 0; q < 16; q++) {
                ull hx = h2[2 * q], hy = h2[2 * q + 1];
#pragma unroll
                for (int r = 0; r < 16; r++) {
                    ulonglong2 wv = *(const ulonglong2*)&ws[r * 256 + kb + q * 4];
                    fma2(acc[r], wv.x, hx);
                    fma2(acc[r], wv.y, hy);
                }
            }
            // write partials: part[kc][r][b], lanes consecutive in b
#pragma unroll
            for (int r = 0; r < 16; r++)
                part[(kc * 16 + r) * 64 + b] = red2(acc[r]);
        }
        __syncthreads();                 // Gs + part ready

        // activation: thread (ab, au) owns one (batch, unit)
        {
            float pre[4];
#pragma unroll
            for (int g = 0; g < 4; g++) {
                int r = g * 4 + au;
                float a = Gs[r * 64 + ab];
                if (s > 0) {
                    a += part[(0 * 16 + r) * 64 + ab];
                    a += part[(1 * 16 + r) * 64 + ab];
                    a += part[(2 * 16 + r) * 64 + ab];
                    a += part[(3 * 16 + r) * 64 + ab];
                }
                pre[g] = a;
            }
            float ig = 1.f / (1.f + expf(-pre[0]));
            float fg = 1.f / (1.f + expf(-pre[1]));
            float gg = tanhf(pre[2]);
            float og = 1.f / (1.f + expf(-pre[3]));
            cst = fg * cst + ig * gg;
            hout[au * 64 + ab] = og * tanhf(cst);
        }
        __syncthreads();                 // hout ready

        if (tid < 64) {
            float4 hv;
            hv.x = hout[0 * 64 + tid];
            hv.y = hout[1 * 64 + tid];
            hv.z = hout[2 * 64 + tid];
            hv.w = hout[3 * 64 + tid];
            *(float4*)&y[((size_t)t * BB + tid) * HID + dir * HH + j0] = hv;
        }
        __syncthreads();                 // y writes done

        if (s + 1 < LL) {
            unsigned tgt = (unsigned)(lbase + s + 1);
            if (tid == 0)
                asm volatile("st.release.gpu.global.u32 [%0], %1;"
                             :: "l"(myflag), "r"(tgt) : "memory");
            if (tid < 64) {
                unsigned* fl = &g_flags[dir * 64 + tid];
                unsigned v;
                do {
                    asm volatile("ld.acquire.gpu.global.u32 %0, [%1];"
                                 : "=r"(v) : "l"(fl));
                } while (v < tgt);
            }
            __syncthreads();
        }
    }
}

// ---------------- FC -----------------------------------------------------------
__global__ void fc_k(const float* __restrict__ feat, const float* __restrict__ Wfc,
                     const float* __restrict__ bfc, float* __restrict__ emit)
{
    int gw = (int)(((size_t)blockIdx.x * blockDim.x + threadIdx.x) >> 5);
    int lane = threadIdx.x & 31;
    if (gw >= LL * BB) return;
    const float* f = feat + (size_t)gw * HID;
    float acc[CC] = {0.f, 0.f, 0.f, 0.f, 0.f};
#pragma unroll
    for (int i = 0; i < HID / 32; i++) {
        int k = lane + i * 32;
        float fv = f[k];
#pragma unroll
        for (int cc = 0; cc < CC; cc++) acc[cc] += fv * Wfc[cc * HID + k];
    }
#pragma unroll
    for (int off = 16; off > 0; off >>= 1)
#pragma unroll
        for (int cc = 0; cc < CC; cc++)
            acc[cc] += __shfl_down_sync(0xffffffffu, acc[cc], off);
    if (lane == 0)
#pragma unroll
        for (int cc = 0; cc < CC; cc++)
            emit[(size_t)gw * CC + cc] = acc[cc] + bfc[cc];
}

// ---------------- Viterbi + backtrace ------------------------------------------
__global__ void viterbi_k(const float* __restrict__ emit, const float* __restrict__ trans,
                          int* __restrict__ bp, float* __restrict__ out, long long osz)
{
    int b = blockIdx.x;
    int lane = threadIdx.x;
    float tr[CC];
    if (lane < CC)
#pragma unroll
        for (int f = 0; f < CC; f++) tr[f] = trans[lane * CC + f];
    float score = (lane == TAG_START) ? 0.f : IMPOSSIBLE_F;

    for (int t = 0; t < LL; t++) {
        float sc[CC];
#pragma unroll
        for (int f = 0; f < CC; f++) sc[f] = __shfl_sync(0xffffffffu, score, f);
        if (lane < CC) {
            float best = sc[0] + tr[0];
            int arg = 0;
#pragma unroll
            for (int f = 1; f < CC; f++) {
                float v = sc[f] + tr[f];
                if (v > best) { best = v; arg = f; }
            }
            bp[((size_t)t * BB + b) * CC + lane] = arg;
            score = best + emit[((size_t)t * BB + b) * CC + lane];
        }
    }
    if (lane < CC) score += trans[TAG_STOP * CC + lane];
    float sc[CC];
#pragma unroll
    for (int f = 0; f < CC; f++) sc[f] = __shfl_sync(0xffffffffu, score, f);
    if (lane == 0) {
        float best = sc[0];
        int tag = 0;
#pragma unroll
        for (int f = 1; f < CC; f++)
            if (sc[f] > best) { best = sc[f]; tag = f; }
        if (b < osz) out[b] = best;
        long long tb = 64;
        long long o = tb + (long long)b * LL + (LL - 1);
        if (o < osz) out[o] = (float)tag;
        for (int t = LL - 1; t >= 1; t--) {
            tag = bp[((size_t)t * BB + b) * CC + tag];
            o = tb + (long long)b * LL + (t - 1);
            if (o < osz) out[o] = (float)tag;
        }
    }
}

// ---------------- features [t][b][k] -> out [b][t][k] --------------------------
__global__ void feat_out_k(const float* __restrict__ feat, float* __restrict__ out,
                           long long osz)
{
    size_t i = (size_t)blockIdx.x * blockDim.x + threadIdx.x;
    size_t total = (size_t)LL * BB * HID / 4;
    if (i >= total) return;
    int k4 = (int)(i % (HID / 4));
    size_t p = i / (HID / 4);
    int b = (int)(p % BB);
    int t = (int)(p / BB);
    long long o = 32832LL + ((long long)b * LL + t) * HID + k4 * 4;
    if (o + 3 < osz)
        *(float4*)&out[o] = *(const float4*)&feat[p * HID + k4 * 4];
}

__global__ void mask_out_k(float* __restrict__ out, long long osz)
{
    long long i = (long long)blockIdx.x * blockDim.x + threadIdx.x;
    if (i >= (long long)BB * LL) return;
    long long o = 16810048LL + i;
    if (o < osz) out[o] = 1.0f;
}

// ---------------- launch --------------------------------------------------------
extern "C" void kernel_launch(void* const* d_in, const int* in_sizes, int n_in,
                              void* d_out, int out_size)
{
    const int*   xs    = (const int*)  d_in[0];
    const float* emb   = (const float*)d_in[1];
    const float* Wih0  = (const float*)d_in[2];
    const float* Whh0  = (const float*)d_in[3];
    const float* b0    = (const float*)d_in[4];
    const float* WihL  = (const float*)d_in[5];
    const float* WhhL  = (const float*)d_in[6];
    const float* bL    = (const float*)d_in[7];
    const float* Wfc   = (const float*)d_in[8];
    const float* bfc   = (const float*)d_in[9];
    const float* trans = (const float*)d_in[10];
    float* out = (float*)d_out;
    long long osz = out_size;

    float *pX, *pA, *pB, *pG, *pE;
    int* pBP;
    cudaGetSymbolAddress((void**)&pX,  g_embx);
    cudaGetSymbolAddress((void**)&pA,  g_bufA);
    cudaGetSymbolAddress((void**)&pB,  g_bufB);
    cudaGetSymbolAddress((void**)&pG,  g_gates);
    cudaGetSymbolAddress((void**)&pE,  g_emit);
    cudaGetSymbolAddress((void**)&pBP, g_bp);

    cudaFuncSetAttribute(lstm_layer_k, cudaFuncAttributeMaxDynamicSharedMemorySize,
                         LSTM_SMEM);
    cudaFuncSetAttribute(gemm_wmma_k, cudaFuncAttributeMaxDynamicSharedMemorySize,
                         GSM_TOT);

    init_bar_k<<<1, 128>>>();

    {
        size_t total = (size_t)LL * BB * (EE / 4);
        embed_k<<<(unsigned)((total + 255) / 256), 256>>>(xs, emb, pX);
    }

    const float* x = pX;
    int K = EE;
    for (int l = 0; l < 4; l++) {
        const float *WihF, *WihB, *WhhF, *WhhB, *bF, *bBk;
        if (l == 0) {
            WihF = Wih0;                 WihB = Wih0 + (size_t)NG * EE;
            WhhF = Whh0;                 WhhB = Whh0 + (size_t)NG * HH;
            bF   = b0;                   bBk  = b0 + NG;
        } else {
            size_t base = (size_t)(l - 1) * 2;
            WihF = WihL + base * NG * HID;       WihB = WihL + (base + 1) * NG * HID;
            WhhF = WhhL + base * NG * HH;        WhhB = WhhL + (base + 1) * NG * HH;
            bF   = bL + base * NG;               bBk  = bL + (base + 1) * NG;
        }
        float* y = (l & 1) ? pB : pA;

        dim3 ggrid(MM / 128, NG / 128, 2);
        gemm_wmma_k<<<ggrid, 256, GSM_TOT>>>(x, WihF, WihB, bF, bBk, pG, K);

        lstm_layer_k<<<128, 256, LSTM_SMEM>>>(pG, WhhF, WhhB, y, l * LL);

        x = y;
        K = HID;
    }

    fc_k<<<(LL * BB * 32) / 256, 256>>>(x, Wfc, bfc, pE);
    viterbi_k<<<BB, 32>>>(pE, trans, pBP, out, osz);
    {
        size_t total = (size_t)LL * BB * HID / 4;
        feat_out_k<<<(unsigned)((total + 255) / 256), 256>>>(x, out, osz);
    }
    mask_out_k<<<(BB * LL + 255) / 256, 256>>>(out, osz);
}

// round 10
// speedup vs baseline: 2.0804x; 1.6329x over previous
#include <cuda_runtime.h>
#include <math.h>
#include <stdint.h>
#include <mma.h>

using namespace nvcuda;

#define LL 512
#define BB 64
#define EE 256
#define HH 256
#define HID 512
#define NG 1024      // 4*H gate rows
#define MM 32768     // LL*BB
#define CC 5
#define TAG_START 3
#define TAG_STOP 4
#define IMPOSSIBLE_F (-1e4f)

typedef unsigned long long ull;

// ---------------- packed fp32x2 FMA helpers (SASS FFMA2, PTX-only) ------------
__device__ __forceinline__ void fma2(ull& acc, ull a, ull b) {
    asm("fma.rn.f32x2 %0, %1, %2, %0;" : "+l"(acc) : "l"(a), "l"(b));
}
__device__ __forceinline__ ull pk2(float x, float y) {
    ull r; asm("mov.b64 %0, {%1, %2};" : "=l"(r) : "f"(x), "f"(y)); return r;
}
__device__ __forceinline__ float red2(ull v) {
    float x, y; asm("mov.b64 {%0, %1}, %2;" : "=f"(x), "=f"(y) : "l"(v)); return x + y;
}
__device__ __forceinline__ float tf32r(float x) {
    uint32_t u; asm("cvt.rna.tf32.f32 %0, %1;" : "=r"(u) : "f"(x));
    return __uint_as_float(u);
}

// ---------------- scratch (device globals; no cudaMalloc allowed) -------------
__device__ float g_embx [(size_t)LL * BB * EE];
__device__ float g_bufA [(size_t)LL * BB * HID];
__device__ float g_bufB [(size_t)LL * BB * HID];
__device__ float g_gates[(size_t)2 * NG * MM];        // G^T: [dir][n][m]
__device__ float g_emit [(size_t)LL * BB * CC];
__device__ int   g_bp   [(size_t)LL * BB * CC];
__device__ unsigned g_flags[128 * 32];                // per-CTA flag, own 128B line

__global__ void init_bar_k() {
    int i = blockIdx.x * blockDim.x + threadIdx.x;
    if (i < 128 * 32) g_flags[i] = 0u;
}

// ---------------- embedding gather --------------------------------------------
__global__ void embed_k(const int* __restrict__ xs, const float* __restrict__ emb,
                        float* __restrict__ X)
{
    size_t i = (size_t)blockIdx.x * blockDim.x + threadIdx.x;
    size_t total = (size_t)LL * BB * (EE / 4);
    if (i >= total) return;
    int e4 = (int)(i % (EE / 4));
    size_t p = i / (EE / 4);
    int b = (int)(p % BB);
    int t = (int)(p / BB);
    int tok = xs[(size_t)b * LL + t];
    *(float4*)&X[p * EE + e4 * 4] = *(const float4*)&emb[(size_t)tok * EE + e4 * 4];
}

// ---------------- wmma tf32 input-projection GEMM, transposed output ----------
// GT[dir][n][m] = A[m,:]·W[dir][n,:] + bias[n]
#define GP 36
#define GBUF (128 * GP)
#define BT_STRIDE 132
#define GSM_TOT ((4 * GBUF + 16 * BT_STRIDE) * 4)     // 82176 bytes

__global__ __launch_bounds__(256) void gemm_wmma_k(
    const float* __restrict__ A,
    const float* __restrict__ W0, const float* __restrict__ W1,
    const float* __restrict__ bias0, const float* __restrict__ bias1,
    float* __restrict__ G, int K)
{
    extern __shared__ float sm[];
    float* Abuf[2] = { sm,             sm + GBUF     };
    float* Wbuf[2] = { sm + 2 * GBUF,  sm + 3 * GBUF };
    float* btile   = sm + 4 * GBUF;                   // [16][132], rows identical

    int tid = threadIdx.x, wid = tid >> 5;
    int m0 = blockIdx.x * 128;
    int n0 = blockIdx.y * 128;
    int dir = blockIdx.z;
    const float* W    = dir ? W1 : W0;
    const float* bias = dir ? bias1 : bias0;
    float* Gt = G + (size_t)dir * NG * MM;

    int wm = wid >> 2;
    int wn = wid & 3;

#pragma unroll
    for (int u = 0; u < 8; u++) {
        int idx = tid + u * 256;
        int r = idx >> 7, c = idx & 127;
        btile[r * BT_STRIDE + c] = bias[n0 + c];
    }

    auto stage = [&](int c, int buf) {
        const float* Asrc = A + (size_t)m0 * K + c * 32;
        const float* Wsrc = W + (size_t)n0 * K + c * 32;
        float* ad = Abuf[buf];
        float* wd = Wbuf[buf];
#pragma unroll
        for (int u = 0; u < 4; u++) {
            int idx = tid + u * 256;
            int row = idx >> 3, c4 = idx & 7;
            float4 v = *(const float4*)&Asrc[(size_t)row * K + c4 * 4];
            v.x = tf32r(v.x); v.y = tf32r(v.y); v.z = tf32r(v.z); v.w = tf32r(v.w);
            *(float4*)&ad[row * GP + c4 * 4] = v;
            float4 q = *(const float4*)&Wsrc[(size_t)row * K + c4 * 4];
            q.x = tf32r(q.x); q.y = tf32r(q.y); q.z = tf32r(q.z); q.w = tf32r(q.w);
            *(float4*)&wd[row * GP + c4 * 4] = q;
        }
    };

    stage(0, 0);
    __syncthreads();

    wmma::fragment<wmma::accumulator, 16, 16, 8, float> acc[4][2];
#pragma unroll
    for (int i = 0; i < 4; i++)
#pragma unroll
        for (int j = 0; j < 2; j++)
            wmma::load_matrix_sync(acc[i][j], btile + wn * 32 + j * 16,
                                   BT_STRIDE, wmma::mem_row_major);

    const int NC = K >> 5;
    for (int c = 0; c < NC; c++) {
        int cur = c & 1;
        if (c + 1 < NC) stage(c + 1, cur ^ 1);

        const float* ab = Abuf[cur] + wm * 64 * GP;
        const float* wb = Wbuf[cur] + wn * 32 * GP;
#pragma unroll
        for (int kk = 0; kk < 4; kk++) {
            wmma::fragment<wmma::matrix_a, 16, 16, 8, wmma::precision::tf32,
                           wmma::row_major> af[4];
            wmma::fragment<wmma::matrix_b, 16, 16, 8, wmma::precision::tf32,
                           wmma::col_major> bf[2];
#pragma unroll
            for (int i = 0; i < 4; i++)
                wmma::load_matrix_sync(af[i], ab + i * 16 * GP + kk * 8, GP);
#pragma unroll
            for (int j = 0; j < 2; j++)
                wmma::load_matrix_sync(bf[j], wb + j * 16 * GP + kk * 8, GP);
#pragma unroll
            for (int i = 0; i < 4; i++)
#pragma unroll
                for (int j = 0; j < 2; j++)
                    wmma::mma_sync(acc[i][j], af[i], bf[j], acc[i][j]);
        }
        __syncthreads();
    }

#pragma unroll
    for (int i = 0; i < 4; i++)
#pragma unroll
        for (int j = 0; j < 2; j++) {
            float* gt = Gt + (size_t)(n0 + wn * 32 + j * 16) * MM
                           + (m0 + wm * 64 + i * 16);
            wmma::store_matrix_sync(gt, acc[i][j], MM, wmma::mem_col_major);
        }
}

// ---------------- persistent per-layer LSTM recurrence ------------------------
// 128 CTAs: dir = bx>>6, unit group j0 = (bx&63)*4. 256 threads:
//   warp w: bh = w&1, kc = w>>1 (k-quarter).  lane -> b = lane + 32*bh.
#define HS_S 260
#define SMW  0                           // ws[16][256]            4096 floats
#define SMH  4096                        // hs[64][HS_S]           16640
#define SMG  (SMH + 64 * HS_S)           // Gs[16][64]             1024
#define SMP  (SMG + 1024)                // part[4][16][64]        4096
#define SMO  (SMP + 4096)                // hout[4][64]            256
#define LSTM_SMEM ((SMO + 256) * 4)      // 104448 bytes

__global__ __launch_bounds__(256, 1) void lstm_layer_k(
    const float* __restrict__ Gt,
    const float* __restrict__ Whh0, const float* __restrict__ Whh1,
    float* __restrict__ y, int lbase)
{
    extern __shared__ float sm[];
    float* ws   = sm + SMW;
    float* hs   = sm + SMH;
    float* Gs   = sm + SMG;
    float* part = sm + SMP;
    float* hout = sm + SMO;

    int bx  = blockIdx.x;
    int dir = bx >> 6;
    int j0  = (bx & 63) * 4;
    int tid = threadIdx.x;
    int lane = tid & 31, wid = tid >> 5;
    int bh = wid & 1, kc = wid >> 1;
    int b  = lane + 32 * bh;
    int kb = kc * 64;
    const float* Whh = dir ? Whh1 : Whh0;
    const float* Gd  = Gt + (size_t)dir * NG * MM;

    // ---- stage Whh rows into smem once: ws[r][k], r = gate*4 + unit ----------
#pragma unroll
    for (int u = 0; u < 4; u++) {
        int idx = tid + u * 256;
        int r = idx >> 6, k4 = idx & 63;
        int g = r >> 2, un = r & 3;
        *(float4*)&ws[r * 256 + k4 * 4] =
            *(const float4*)&Whh[(size_t)(g * 256 + j0 + un) * HH + k4 * 4];
    }

    int ab = tid & 63, au = tid >> 6;
    float cst = 0.f;

    size_t gaddr[4];
    int grow[4], gbv[4];
#pragma unroll
    for (int u = 0; u < 4; u++) {
        int v = tid + u * 256;
        int r = v >> 6, bb = v & 63;
        grow[u] = r; gbv[u] = bb;
        gaddr[u] = (size_t)((r >> 2) * 256 + j0 + (r & 3)) * MM + bb;
    }

    unsigned* myflag = &g_flags[(dir * 64 + (bx & 63)) * 32];
    __syncthreads();                     // ws ready

    // preload input-projection gates for s = 0
    float glo[4];
    {
        int t0 = dir ? (LL - 1) : 0;
#pragma unroll
        for (int u = 0; u < 4; u++)
            glo[u] = Gd[gaddr[u] + (size_t)t0 * 64];
    }

    for (int s = 0; s < LL; s++) {
        int t     = dir ? (LL - 1 - s) : s;
        int tprev = dir ? (t + 1) : (t - 1);

        if (s > 0) {
            // stage h_prev: 64 b x 256 k = 4096 float4, 16 per thread
            const float* yb = y + ((size_t)tprev * BB) * HID + dir * HH;
#pragma unroll
            for (int u = 0; u < 16; u++) {
                int v = tid + u * 256;
                int b2 = v >> 6, k4 = v & 63;
                float4 hv = *(const float4*)&yb[(size_t)b2 * HID + k4 * 4];
                *(float4*)&hs[b2 * HS_S + k4 * 4] = hv;
            }
        }
        __syncthreads();                 // hs ready

#pragma unroll
        for (int u = 0; u < 4; u++)
            Gs[grow[u] * 64 + gbv[u]] = glo[u];

        if (s > 0) {
            ull h2[32];
#pragma unroll
            for (int q = 0; q < 16; q++) {
                ulonglong2 hv = *(const ulonglong2*)&hs[b * HS_S + kb + q * 4];
                h2[2 * q] = hv.x; h2[2 * q + 1] = hv.y;
            }
            ull acc[16];
#pragma unroll
            for (int r = 0; r < 16; r++) acc[r] = pk2(0.f, 0.f);
#pragma unroll
            for (int q = 0; q < 16; q++) {
                ull hx = h2[2 * q], hy = h2[2 * q + 1];
#pragma unroll
                for (int r = 0; r < 16; r++) {
                    ulonglong2 wv = *(const ulonglong2*)&ws[r * 256 + kb + q * 4];
                    fma2(acc[r], wv.x, hx);
                    fma2(acc[r], wv.y, hy);
                }
            }
#pragma unroll
            for (int r = 0; r < 16; r++)
                part[(kc * 16 + r) * 64 + b] = red2(acc[r]);
        }
        __syncthreads();                 // Gs + part ready

        {
            float pre[4];
#pragma unroll
            for (int g = 0; g < 4; g++) {
                int r = g * 4 + au;
                float a = Gs[r * 64 + ab];
                if (s > 0) {
                    a += part[(0 * 16 + r) * 64 + ab];
                    a += part[(1 * 16 + r) * 64 + ab];
                    a += part[(2 * 16 + r) * 64 + ab];
                    a += part[(3 * 16 + r) * 64 + ab];
                }
                pre[g] = a;
            }
            float ig = 1.f / (1.f + expf(-pre[0]));
            float fg = 1.f / (1.f + expf(-pre[1]));
            float gg = tanhf(pre[2]);
            float og = 1.f / (1.f + expf(-pre[3]));
            cst = fg * cst + ig * gg;
            hout[au * 64 + ab] = og * tanhf(cst);
        }
        __syncthreads();                 // hout ready

        if (tid < 64) {
            float4 hv;
            hv.x = hout[0 * 64 + tid];
            hv.y = hout[1 * 64 + tid];
            hv.z = hout[2 * 64 + tid];
            hv.w = hout[3 * 64 + tid];
            *(float4*)&y[((size_t)t * BB + tid) * HID + dir * HH + j0] = hv;
        }
        __syncthreads();                 // y writes done

        if (s + 1 < LL) {
            // prefetch next step's gates BEFORE the spin (independent of flags)
            int tn = dir ? (LL - 2 - s) : (s + 1);
#pragma unroll
            for (int u = 0; u < 4; u++)
                glo[u] = Gd[gaddr[u] + (size_t)tn * 64];

            unsigned tgt = (unsigned)(lbase + s + 1);
            if (tid == 0)
                asm volatile("st.release.gpu.global.u32 [%0], %1;"
                             :: "l"(myflag), "r"(tgt) : "memory");
            if (tid < 64) {
                unsigned* fl = &g_flags[(dir * 64 + tid) * 32];
                unsigned v;
                asm volatile("ld.acquire.gpu.global.u32 %0, [%1];"
                             : "=r"(v) : "l"(fl));
                while (v < tgt) {
                    __nanosleep(64);
                    asm volatile("ld.acquire.gpu.global.u32 %0, [%1];"
                                 : "=r"(v) : "l"(fl));
                }
            }
            __syncthreads();
        }
    }
}

// ---------------- FC -----------------------------------------------------------
__global__ void fc_k(const float* __restrict__ feat, const float* __restrict__ Wfc,
                     const float* __restrict__ bfc, float* __restrict__ emit)
{
    int gw = (int)(((size_t)blockIdx.x * blockDim.x + threadIdx.x) >> 5);
    int lane = threadIdx.x & 31;
    if (gw >= LL * BB) return;
    const float* f = feat + (size_t)gw * HID;
    float acc[CC] = {0.f, 0.f, 0.f, 0.f, 0.f};
#pragma unroll
    for (int i = 0; i < HID / 32; i++) {
        int k = lane + i * 32;
        float fv = f[k];
#pragma unroll
        for (int cc = 0; cc < CC; cc++) acc[cc] += fv * Wfc[cc * HID + k];
    }
#pragma unroll
    for (int off = 16; off > 0; off >>= 1)
#pragma unroll
        for (int cc = 0; cc < CC; cc++)
            acc[cc] += __shfl_down_sync(0xffffffffu, acc[cc], off);
    if (lane == 0)
#pragma unroll
        for (int cc = 0; cc < CC; cc++)
            emit[(size_t)gw * CC + cc] = acc[cc] + bfc[cc];
}

// ---------------- Viterbi + backtrace ------------------------------------------
__global__ void viterbi_k(const float* __restrict__ emit, const float* __restrict__ trans,
                          int* __restrict__ bp, float* __restrict__ out, long long osz)
{
    int b = blockIdx.x;
    int lane = threadIdx.x;
    float tr[CC];
    if (lane < CC)
#pragma unroll
        for (int f = 0; f < CC; f++) tr[f] = trans[lane * CC + f];
    float score = (lane == TAG_START) ? 0.f : IMPOSSIBLE_F;

    for (int t = 0; t < LL; t++) {
        float sc[CC];
#pragma unroll
        for (int f = 0; f < CC; f++) sc[f] = __shfl_sync(0xffffffffu, score, f);
        if (lane < CC) {
            float best = sc[0] + tr[0];
            int arg = 0;
#pragma unroll
            for (int f = 1; f < CC; f++) {
                float v = sc[f] + tr[f];
                if (v > best) { best = v; arg = f; }
            }
            bp[((size_t)t * BB + b) * CC + lane] = arg;
            score = best + emit[((size_t)t * BB + b) * CC + lane];
        }
    }
    if (lane < CC) score += trans[TAG_STOP * CC + lane];
    float sc[CC];
#pragma unroll
    for (int f = 0; f < CC; f++) sc[f] = __shfl_sync(0xffffffffu, score, f);
    if (lane == 0) {
        float best = sc[0];
        int tag = 0;
#pragma unroll
        for (int f = 1; f < CC; f++)
            if (sc[f] > best) { best = sc[f]; tag = f; }
        if (b < osz) out[b] = best;
        long long tb = 64;
        long long o = tb + (long long)b * LL + (LL - 1);
        if (o < osz) out[o] = (float)tag;
        for (int t = LL - 1; t >= 1; t--) {
            tag = bp[((size_t)t * BB + b) * CC + tag];
            o = tb + (long long)b * LL + (t - 1);
            if (o < osz) out[o] = (float)tag;
        }
    }
}

// ---------------- features [t][b][k] -> out [b][t][k] --------------------------
__global__ void feat_out_k(const float* __restrict__ feat, float* __restrict__ out,
                           long long osz)
{
    size_t i = (size_t)blockIdx.x * blockDim.x + threadIdx.x;
    size_t total = (size_t)LL * BB * HID / 4;
    if (i >= total) return;
    int k4 = (int)(i % (HID / 4));
    size_t p = i / (HID / 4);
    int b = (int)(p % BB);
    int t = (int)(p / BB);
    long long o = 32832LL + ((long long)b * LL + t) * HID + k4 * 4;
    if (o + 3 < osz)
        *(float4*)&out[o] = *(const float4*)&feat[p * HID + k4 * 4];
}

__global__ void mask_out_k(float* __restrict__ out, long long osz)
{
    long long i = (long long)blockIdx.x * blockDim.x + threadIdx.x;
    if (i >= (long long)BB * LL) return;
    long long o = 16810048LL + i;
    if (o < osz) out[o] = 1.0f;
}

// ---------------- launch --------------------------------------------------------
extern "C" void kernel_launch(void* const* d_in, const int* in_sizes, int n_in,
                              void* d_out, int out_size)
{
    const int*   xs    = (const int*)  d_in[0];
    const float* emb   = (const float*)d_in[1];
    const float* Wih0  = (const float*)d_in[2];
    const float* Whh0  = (const float*)d_in[3];
    const float* b0    = (const float*)d_in[4];
    const float* WihL  = (const float*)d_in[5];
    const float* WhhL  = (const float*)d_in[6];
    const float* bL    = (const float*)d_in[7];
    const float* Wfc   = (const float*)d_in[8];
    const float* bfc   = (const float*)d_in[9];
    const float* trans = (const float*)d_in[10];
    float* out = (float*)d_out;
    long long osz = out_size;

    float *pX, *pA, *pB, *pG, *pE;
    int* pBP;
    cudaGetSymbolAddress((void**)&pX,  g_embx);
    cudaGetSymbolAddress((void**)&pA,  g_bufA);
    cudaGetSymbolAddress((void**)&pB,  g_bufB);
    cudaGetSymbolAddress((void**)&pG,  g_gates);
    cudaGetSymbolAddress((void**)&pE,  g_emit);
    cudaGetSymbolAddress((void**)&pBP, g_bp);

    cudaFuncSetAttribute(lstm_layer_k, cudaFuncAttributeMaxDynamicSharedMemorySize,
                         LSTM_SMEM);
    cudaFuncSetAttribute(gemm_wmma_k, cudaFuncAttributeMaxDynamicSharedMemorySize,
                         GSM_TOT);

    init_bar_k<<<16, 256>>>();

    {
        size_t total = (size_t)LL * BB * (EE / 4);
        embed_k<<<(unsigned)((total + 255) / 256), 256>>>(xs, emb, pX);
    }

    const float* x = pX;
    int K = EE;
    for (int l = 0; l < 4; l++) {
        const float *WihF, *WihB, *WhhF, *WhhB, *bF, *bBk;
        if (l == 0) {
            WihF = Wih0;                 WihB = Wih0 + (size_t)NG * EE;
            WhhF = Whh0;                 WhhB = Whh0 + (size_t)NG * HH;
            bF   = b0;                   bBk  = b0 + NG;
        } else {
            size_t base = (size_t)(l - 1) * 2;
            WihF = WihL + base * NG * HID;       WihB = WihL + (base + 1) * NG * HID;
            WhhF = WhhL + base * NG * HH;        WhhB = WhhL + (base + 1) * NG * HH;
            bF   = bL + base * NG;               bBk  = bL + (base + 1) * NG;
        }
        float* y = (l & 1) ? pB : pA;

        dim3 ggrid(MM / 128, NG / 128, 2);
        gemm_wmma_k<<<ggrid, 256, GSM_TOT>>>(x, WihF, WihB, bF, bBk, pG, K);

        lstm_layer_k<<<128, 256, LSTM_SMEM>>>(pG, WhhF, WhhB, y, l * LL);

        x = y;
        K = HID;
    }

    fc_k<<<(LL * BB * 32) / 256, 256>>>(x, Wfc, bfc, pE);
    viterbi_k<<<BB, 32>>>(pE, trans, pBP, out, osz);
    {
        size_t total = (size_t)LL * BB * HID / 4;
        feat_out_k<<<(unsigned)((total + 255) / 256), 256>>>(x, out, osz);
    }
    mask_out_k<<<(BB * LL + 255) / 256, 256>>>(out, osz);
}

// round 11
// speedup vs baseline: 2.2718x; 1.0920x over previous
#include <cuda_runtime.h>
#include <math.h>
#include <stdint.h>
#include <mma.h>

using namespace nvcuda;

#define LL 512
#define BB 64
#define EE 256
#define HH 256
#define HID 512
#define NG 1024      // 4*H gate rows
#define MM 32768     // LL*BB
#define CC 5
#define TAG_START 3
#define TAG_STOP 4
#define IMPOSSIBLE_F (-1e4f)

typedef unsigned long long ull;

__device__ __forceinline__ float tf32r(float x) {
    uint32_t u; asm("cvt.rna.tf32.f32 %0, %1;" : "=r"(u) : "f"(x));
    return __uint_as_float(u);
}
__device__ __forceinline__ float tanh_a(float x) {
    float r; asm("tanh.approx.f32 %0, %1;" : "=f"(r) : "f"(x)); return r;
}

// ---------------- scratch (device globals; no cudaMalloc allowed) -------------
__device__ float g_embx [(size_t)LL * BB * EE];
__device__ float g_bufA [(size_t)LL * BB * HID];
__device__ float g_bufB [(size_t)LL * BB * HID];
__device__ float g_gates[(size_t)2 * NG * MM];        // G^T: [dir][n][m]
__device__ float g_emit [(size_t)LL * BB * CC];
__device__ int   g_bp   [(size_t)LL * BB * CC];
__device__ unsigned g_flags[128 * 32];                // per-CTA flag, own 128B line

__global__ void init_bar_k() {
    int i = blockIdx.x * blockDim.x + threadIdx.x;
    if (i < 128 * 32) g_flags[i] = 0u;
}

// ---------------- embedding gather --------------------------------------------
__global__ void embed_k(const int* __restrict__ xs, const float* __restrict__ emb,
                        float* __restrict__ X)
{
    size_t i = (size_t)blockIdx.x * blockDim.x + threadIdx.x;
    size_t total = (size_t)LL * BB * (EE / 4);
    if (i >= total) return;
    int e4 = (int)(i % (EE / 4));
    size_t p = i / (EE / 4);
    int b = (int)(p % BB);
    int t = (int)(p / BB);
    int tok = xs[(size_t)b * LL + t];
    *(float4*)&X[p * EE + e4 * 4] = *(const float4*)&emb[(size_t)tok * EE + e4 * 4];
}

// ---------------- wmma tf32 input-projection GEMM, transposed output ----------
// GT[dir][n][m] = A[m,:]·W[dir][n,:] + bias[n]
#define GP 36
#define GBUF (128 * GP)
#define BT_STRIDE 132
#define GSM_TOT ((4 * GBUF + 16 * BT_STRIDE) * 4)     // 82176 bytes

__global__ __launch_bounds__(256) void gemm_wmma_k(
    const float* __restrict__ A,
    const float* __restrict__ W0, const float* __restrict__ W1,
    const float* __restrict__ bias0, const float* __restrict__ bias1,
    float* __restrict__ G, int K)
{
    extern __shared__ float sm[];
    float* Abuf[2] = { sm,             sm + GBUF     };
    float* Wbuf[2] = { sm + 2 * GBUF,  sm + 3 * GBUF };
    float* btile   = sm + 4 * GBUF;                   // [16][132], rows identical

    int tid = threadIdx.x, wid = tid >> 5;
    int m0 = blockIdx.x * 128;
    int n0 = blockIdx.y * 128;
    int dir = blockIdx.z;
    const float* W    = dir ? W1 : W0;
    const float* bias = dir ? bias1 : bias0;
    float* Gt = G + (size_t)dir * NG * MM;

    int wm = wid >> 2;
    int wn = wid & 3;

#pragma unroll
    for (int u = 0; u < 8; u++) {
        int idx = tid + u * 256;
        int r = idx >> 7, c = idx & 127;
        btile[r * BT_STRIDE + c] = bias[n0 + c];
    }

    auto stage = [&](int c, int buf) {
        const float* Asrc = A + (size_t)m0 * K + c * 32;
        const float* Wsrc = W + (size_t)n0 * K + c * 32;
        float* ad = Abuf[buf];
        float* wd = Wbuf[buf];
#pragma unroll
        for (int u = 0; u < 4; u++) {
            int idx = tid + u * 256;
            int row = idx >> 3, c4 = idx & 7;
            float4 v = *(const float4*)&Asrc[(size_t)row * K + c4 * 4];
            v.x = tf32r(v.x); v.y = tf32r(v.y); v.z = tf32r(v.z); v.w = tf32r(v.w);
            *(float4*)&ad[row * GP + c4 * 4] = v;
            float4 q = *(const float4*)&Wsrc[(size_t)row * K + c4 * 4];
            q.x = tf32r(q.x); q.y = tf32r(q.y); q.z = tf32r(q.z); q.w = tf32r(q.w);
            *(float4*)&wd[row * GP + c4 * 4] = q;
        }
    };

    stage(0, 0);
    __syncthreads();

    wmma::fragment<wmma::accumulator, 16, 16, 8, float> acc[4][2];
#pragma unroll
    for (int i = 0; i < 4; i++)
#pragma unroll
        for (int j = 0; j < 2; j++)
            wmma::load_matrix_sync(acc[i][j], btile + wn * 32 + j * 16,
                                   BT_STRIDE, wmma::mem_row_major);

    const int NC = K >> 5;
    for (int c = 0; c < NC; c++) {
        int cur = c & 1;
        if (c + 1 < NC) stage(c + 1, cur ^ 1);

        const float* ab = Abuf[cur] + wm * 64 * GP;
        const float* wb = Wbuf[cur] + wn * 32 * GP;
#pragma unroll
        for (int kk = 0; kk < 4; kk++) {
            wmma::fragment<wmma::matrix_a, 16, 16, 8, wmma::precision::tf32,
                           wmma::row_major> af[4];
            wmma::fragment<wmma::matrix_b, 16, 16, 8, wmma::precision::tf32,
                           wmma::col_major> bf[2];
#pragma unroll
            for (int i = 0; i < 4; i++)
                wmma::load_matrix_sync(af[i], ab + i * 16 * GP + kk * 8, GP);
#pragma unroll
            for (int j = 0; j < 2; j++)
                wmma::load_matrix_sync(bf[j], wb + j * 16 * GP + kk * 8, GP);
#pragma unroll
            for (int i = 0; i < 4; i++)
#pragma unroll
                for (int j = 0; j < 2; j++)
                    wmma::mma_sync(acc[i][j], af[i], bf[j], acc[i][j]);
        }
        __syncthreads();
    }

#pragma unroll
    for (int i = 0; i < 4; i++)
#pragma unroll
        for (int j = 0; j < 2; j++) {
            float* gt = Gt + (size_t)(n0 + wn * 32 + j * 16) * MM
                           + (m0 + wm * 64 + i * 16);
            wmma::store_matrix_sync(gt, acc[i][j], MM, wmma::mem_col_major);
        }
}

// ---------------- persistent per-layer LSTM recurrence (tensor-core dot) ------
// 128 CTAs: dir = bx>>6, unit group j0 = (bx&63)*4.
// Dot: out[64b][16r] = hs[64][256] @ ws2[256][16]  via wmma tf32.
//   warp w: mt = w&3 (16-batch tile), kh = w>>2 (K half). 16 mma of 16x16x8.
// Partials part[w][16m][16r] (ld 20) summed in activation (thread = (b, unit)).
#define HS_S  264                        // hs row stride, multiple of 8
#define WS_LD 20                         // ws2 [256][WS_LD] row-major (k, r)
#define P_LD  20                         // part tile ld
#define SM_WS 0                          // 256*20 = 5120 floats
#define SM_HS 5120                       // 64*264 = 16896
#define SM_GS (SM_HS + 64 * HS_S)        // 16*64 = 1024
#define SM_PT (SM_GS + 1024)             // 8*16*20 = 2560
#define SM_HO (SM_PT + 2560)             // 256
#define LSTM_SMEM ((SM_HO + 256) * 4)    // 103424 bytes

__global__ __launch_bounds__(256, 1) void lstm_layer_k(
    const float* __restrict__ Gt,
    const float* __restrict__ Whh0, const float* __restrict__ Whh1,
    float* __restrict__ y, int lbase)
{
    extern __shared__ float sm[];
    float* ws2  = sm + SM_WS;
    float* hs   = sm + SM_HS;
    float* Gs   = sm + SM_GS;
    float* part = sm + SM_PT;
    float* hout = sm + SM_HO;

    int bx  = blockIdx.x;
    int dir = bx >> 6;
    int j0  = (bx & 63) * 4;
    int tid = threadIdx.x;
    int wid = tid >> 5;
    int mt = wid & 3, kh = wid >> 2;
    const float* Whh = dir ? Whh1 : Whh0;
    const float* Gd  = Gt + (size_t)dir * NG * MM;

    // ---- stage Whh transposed into smem once: ws2[k][r], tf32-rounded -------
#pragma unroll
    for (int u = 0; u < 16; u++) {
        int idx = tid + u * 256;         // 4096 scalars
        int k = idx >> 4, r = idx & 15;
        int g = r >> 2, un = r & 3;
        ws2[k * WS_LD + r] = tf32r(Whh[(size_t)(g * 256 + j0 + un) * HH + k]);
    }

    int ab = tid & 63, au = tid >> 6;    // activation identity: (batch, unit)
    int am = ab & 15, amt = ab >> 4;
    float cst = 0.f;

    size_t gaddr[4];
    int grow[4], gbv[4];
#pragma unroll
    for (int u = 0; u < 4; u++) {
        int v = tid + u * 256;
        int r = v >> 6, bb = v & 63;
        grow[u] = r; gbv[u] = bb;
        gaddr[u] = (size_t)((r >> 2) * 256 + j0 + (r & 3)) * MM + bb;
    }

    unsigned* myflag = &g_flags[(dir * 64 + (bx & 63)) * 32];
    __syncthreads();                     // ws2 ready

    // preload input-projection gates for s = 0
    float glo[4];
    {
        int t0 = dir ? (LL - 1) : 0;
#pragma unroll
        for (int u = 0; u < 4; u++)
            glo[u] = Gd[gaddr[u] + (size_t)t0 * 64];
    }

    for (int s = 0; s < LL; s++) {
        int t     = dir ? (LL - 1 - s) : s;
        int tprev = dir ? (t + 1) : (t - 1);

        if (s > 0) {
            // stage h_prev: 64 b x 256 k = 4096 float4, 16 per thread
            const float* yb = y + ((size_t)tprev * BB) * HID + dir * HH;
#pragma unroll
            for (int u = 0; u < 16; u++) {
                int v = tid + u * 256;
                int b2 = v >> 6, k4 = v & 63;
                float4 hv = *(const float4*)&yb[(size_t)b2 * HID + k4 * 4];
                *(float4*)&hs[b2 * HS_S + k4 * 4] = hv;
            }
        }
#pragma unroll
        for (int u = 0; u < 4; u++)
            Gs[grow[u] * 64 + gbv[u]] = glo[u];
        __syncthreads();                 // hs + Gs ready

        if (s > 0) {
            // wmma dot: warp (mt, kh) -> part[w] = hs[mt][khalf] @ ws2[khalf]
            wmma::fragment<wmma::accumulator, 16, 16, 8, float> acc;
            wmma::fill_fragment(acc, 0.f);
            const float* hb = hs + mt * 16 * HS_S + kh * 128;
            const float* wb = ws2 + kh * 128 * WS_LD;
#pragma unroll
            for (int kf = 0; kf < 16; kf++) {
                wmma::fragment<wmma::matrix_a, 16, 16, 8, wmma::precision::tf32,
                               wmma::row_major> af;
                wmma::fragment<wmma::matrix_b, 16, 16, 8, wmma::precision::tf32,
                               wmma::row_major> bf;
                wmma::load_matrix_sync(af, hb + kf * 8, HS_S);
#pragma unroll
                for (int e = 0; e < af.num_elements; e++)
                    af.x[e] = wmma::__float_to_tf32(af.x[e]);
                wmma::load_matrix_sync(bf, wb + kf * 8 * WS_LD, WS_LD);
                wmma::mma_sync(acc, af, bf, acc);
            }
            wmma::store_matrix_sync(part + wid * (16 * P_LD), acc, P_LD,
                                    wmma::mem_row_major);
        }
        __syncthreads();                 // part ready

        // activation: thread (ab, au) owns one (batch, unit)
        {
            float pre[4];
#pragma unroll
            for (int g = 0; g < 4; g++) {
                int r = g * 4 + au;
                float a = Gs[r * 64 + ab];
                if (s > 0) {
                    a += part[(0 * 4 + amt) * (16 * P_LD) + am * P_LD + r];
                    a += part[(1 * 4 + amt) * (16 * P_LD) + am * P_LD + r];
                }
                pre[g] = a;
            }
            float ig = 0.5f * (1.f + tanh_a(0.5f * pre[0]));
            float fg = 0.5f * (1.f + tanh_a(0.5f * pre[1]));
            float gg = tanh_a(pre[2]);
            float og = 0.5f * (1.f + tanh_a(0.5f * pre[3]));
            cst = fg * cst + ig * gg;
            hout[au * 64 + ab] = og * tanh_a(cst);
        }
        __syncthreads();                 // hout ready

        if (tid < 64) {
            float4 hv;
            hv.x = hout[0 * 64 + tid];
            hv.y = hout[1 * 64 + tid];
            hv.z = hout[2 * 64 + tid];
            hv.w = hout[3 * 64 + tid];
            *(float4*)&y[((size_t)t * BB + tid) * HID + dir * HH + j0] = hv;
        }
        __syncthreads();                 // y writes done

        if (s + 1 < LL) {
            // prefetch next step's gates BEFORE the spin
            int tn = dir ? (LL - 2 - s) : (s + 1);
#pragma unroll
            for (int u = 0; u < 4; u++)
                glo[u] = Gd[gaddr[u] + (size_t)tn * 64];

            unsigned tgt = (unsigned)(lbase + s + 1);
            if (tid == 0)
                asm volatile("st.release.gpu.global.u32 [%0], %1;"
                             :: "l"(myflag), "r"(tgt) : "memory");
            if (tid < 64) {
                unsigned* fl = &g_flags[(dir * 64 + tid) * 32];
                unsigned v;
                do {
                    asm volatile("ld.acquire.gpu.global.u32 %0, [%1];"
                                 : "=r"(v) : "l"(fl));
                } while (v < tgt);
            }
            __syncthreads();
        }
    }
}

// ---------------- FC -----------------------------------------------------------
__global__ void fc_k(const float* __restrict__ feat, const float* __restrict__ Wfc,
                     const float* __restrict__ bfc, float* __restrict__ emit)
{
    int gw = (int)(((size_t)blockIdx.x * blockDim.x + threadIdx.x) >> 5);
    int lane = threadIdx.x & 31;
    if (gw >= LL * BB) return;
    const float* f = feat + (size_t)gw * HID;
    float acc[CC] = {0.f, 0.f, 0.f, 0.f, 0.f};
#pragma unroll
    for (int i = 0; i < HID / 32; i++) {
        int k = lane + i * 32;
        float fv = f[k];
#pragma unroll
        for (int cc = 0; cc < CC; cc++) acc[cc] += fv * Wfc[cc * HID + k];
    }
#pragma unroll
    for (int off = 16; off > 0; off >>= 1)
#pragma unroll
        for (int cc = 0; cc < CC; cc++)
            acc[cc] += __shfl_down_sync(0xffffffffu, acc[cc], off);
    if (lane == 0)
#pragma unroll
        for (int cc = 0; cc < CC; cc++)
            emit[(size_t)gw * CC + cc] = acc[cc] + bfc[cc];
}

// ---------------- Viterbi + backtrace ------------------------------------------
__global__ void viterbi_k(const float* __restrict__ emit, const float* __restrict__ trans,
                          int* __restrict__ bp, float* __restrict__ out, long long osz)
{
    int b = blockIdx.x;
    int lane = threadIdx.x;
    float tr[CC];
    if (lane < CC)
#pragma unroll
        for (int f = 0; f < CC; f++) tr[f] = trans[lane * CC + f];
    float score = (lane == TAG_START) ? 0.f : IMPOSSIBLE_F;

    for (int t = 0; t < LL; t++) {
        float sc[CC];
#pragma unroll
        for (int f = 0; f < CC; f++) sc[f] = __shfl_sync(0xffffffffu, score, f);
        if (lane < CC) {
            float best = sc[0] + tr[0];
            int arg = 0;
#pragma unroll
            for (int f = 1; f < CC; f++) {
                float v = sc[f] + tr[f];
                if (v > best) { best = v; arg = f; }
            }
            bp[((size_t)t * BB + b) * CC + lane] = arg;
            score = best + emit[((size_t)t * BB + b) * CC + lane];
        }
    }
    if (lane < CC) score += trans[TAG_STOP * CC + lane];
    float sc[CC];
#pragma unroll
    for (int f = 0; f < CC; f++) sc[f] = __shfl_sync(0xffffffffu, score, f);
    if (lane == 0) {
        float best = sc[0];
        int tag = 0;
#pragma unroll
        for (int f = 1; f < CC; f++)
            if (sc[f] > best) { best = sc[f]; tag = f; }
        if (b < osz) out[b] = best;
        long long tb = 64;
        long long o = tb + (long long)b * LL + (LL - 1);
        if (o < osz) out[o] = (float)tag;
        for (int t = LL - 1; t >= 1; t--) {
            tag = bp[((size_t)t * BB + b) * CC + tag];
            o = tb + (long long)b * LL + (t - 1);
            if (o < osz) out[o] = (float)tag;
        }
    }
}

// ---------------- features [t][b][k] -> out [b][t][k] --------------------------
__global__ void feat_out_k(const float* __restrict__ feat, float* __restrict__ out,
                           long long osz)
{
    size_t i = (size_t)blockIdx.x * blockDim.x + threadIdx.x;
    size_t total = (size_t)LL * BB * HID / 4;
    if (i >= total) return;
    int k4 = (int)(i % (HID / 4));
    size_t p = i / (HID / 4);
    int b = (int)(p % BB);
    int t = (int)(p / BB);
    long long o = 32832LL + ((long long)b * LL + t) * HID + k4 * 4;
    if (o + 3 < osz)
        *(float4*)&out[o] = *(const float4*)&feat[p * HID + k4 * 4];
}

__global__ void mask_out_k(float* __restrict__ out, long long osz)
{
    long long i = (long long)blockIdx.x * blockDim.x + threadIdx.x;
    if (i >= (long long)BB * LL) return;
    long long o = 16810048LL + i;
    if (o < osz) out[o] = 1.0f;
}

// ---------------- launch --------------------------------------------------------
extern "C" void kernel_launch(void* const* d_in, const int* in_sizes, int n_in,
                              void* d_out, int out_size)
{
    const int*   xs    = (const int*)  d_in[0];
    const float* emb   = (const float*)d_in[1];
    const float* Wih0  = (const float*)d_in[2];
    const float* Whh0  = (const float*)d_in[3];
    const float* b0    = (const float*)d_in[4];
    const float* WihL  = (const float*)d_in[5];
    const float* WhhL  = (const float*)d_in[6];
    const float* bL    = (const float*)d_in[7];
    const float* Wfc   = (const float*)d_in[8];
    const float* bfc   = (const float*)d_in[9];
    const float* trans = (const float*)d_in[10];
    float* out = (float*)d_out;
    long long osz = out_size;

    float *pX, *pA, *pB, *pG, *pE;
    int* pBP;
    cudaGetSymbolAddress((void**)&pX,  g_embx);
    cudaGetSymbolAddress((void**)&pA,  g_bufA);
    cudaGetSymbolAddress((void**)&pB,  g_bufB);
    cudaGetSymbolAddress((void**)&pG,  g_gates);
    cudaGetSymbolAddress((void**)&pE,  g_emit);
    cudaGetSymbolAddress((void**)&pBP, g_bp);

    cudaFuncSetAttribute(lstm_layer_k, cudaFuncAttributeMaxDynamicSharedMemorySize,
                         LSTM_SMEM);
    cudaFuncSetAttribute(gemm_wmma_k, cudaFuncAttributeMaxDynamicSharedMemorySize,
                         GSM_TOT);

    init_bar_k<<<16, 256>>>();

    {
        size_t total = (size_t)LL * BB * (EE / 4);
        embed_k<<<(unsigned)((total + 255) / 256), 256>>>(xs, emb, pX);
    }

    const float* x = pX;
    int K = EE;
    for (int l = 0; l < 4; l++) {
        const float *WihF, *WihB, *WhhF, *WhhB, *bF, *bBk;
        if (l == 0) {
            WihF = Wih0;                 WihB = Wih0 + (size_t)NG * EE;
            WhhF = Whh0;                 WhhB = Whh0 + (size_t)NG * HH;
            bF   = b0;                   bBk  = b0 + NG;
        } else {
            size_t base = (size_t)(l - 1) * 2;
            WihF = WihL + base * NG * HID;       WihB = WihL + (base + 1) * NG * HID;
            WhhF = WhhL + base * NG * HH;        WhhB = WhhL + (base + 1) * NG * HH;
            bF   = bL + base * NG;               bBk  = bL + (base + 1) * NG;
        }
        float* y = (l & 1) ? pB : pA;

        dim3 ggrid(MM / 128, NG / 128, 2);
        gemm_wmma_k<<<ggrid, 256, GSM_TOT>>>(x, WihF, WihB, bF, bBk, pG, K);

        lstm_layer_k<<<128, 256, LSTM_SMEM>>>(pG, WhhF, WhhB, y, l * LL);

        x = y;
        K = HID;
    }

    fc_k<<<(LL * BB * 32) / 256, 256>>>(x, Wfc, bfc, pE);
    viterbi_k<<<BB, 32>>>(pE, trans, pBP, out, osz);
    {
        size_t total = (size_t)LL * BB * HID / 4;
        feat_out_k<<<(unsigned)((total + 255) / 256), 256>>>(x, out, osz);
    }
    mask_out_k<<<(BB * LL + 255) / 256, 256>>>(out, osz);
}